// round 1
// baseline (speedup 1.0000x reference)
#include <cuda_runtime.h>
#include <math.h>

#define B_ 32
#define D_ 768
#define L_ 12
#define HEADS_ 12
#define DH_ 64
#define MLP_ 3072
#define NC_ 1000
#define N_ 197
#define NP_ 196
#define MTOK (B_*N_)       // 6304
#define MPATCH (B_*NP_)    // 6272
#define SROW (N_*N_)       // 38809

// ---------------- scratch (device globals; no runtime allocation) ----------
__device__ float g_x [MTOK*D_];
__device__ float g_h [MTOK*D_];
__device__ float g_q [MTOK*D_];
__device__ float g_k [MTOK*D_];
__device__ float g_v [MTOK*D_];
__device__ float g_o [MTOK*D_];
__device__ float g_mlp[(long long)MTOK*MLP_];
__device__ float g_sc [(long long)B_*HEADS_*SROW];
__device__ float g_col[(long long)MPATCH*768];
__device__ float g_po [(long long)MPATCH*D_];
__device__ float g_pool[B_*D_];
__device__ float g_pln [B_*D_];

__device__ __forceinline__ float gelu_f(float x) {
    float x3 = x*x*x;
    return 0.5f*x*(1.0f + tanhf(0.7978845608028654f*(x + 0.044715f*x3)));
}

// ---------------- generic batched SGEMM ------------------------------------
// C[M,N] = A[M,K] @ (TRANSB ? B[N,K]^T : B[K,N]) (+bias) (+gelu | +residual)
// Batch index z decomposes as (z/zdiv, z%zdiv) with independent strides,
// so per-(batch,head) slices of [B,N,D] tensors work without a linear stride.
// EPI: 0 = bias, 1 = bias+gelu, 2 = bias+residual
template<bool TRANSB, int EPI>
__global__ void gemm_kernel(const float* __restrict__ A, const float* __restrict__ Bm,
                            const float* __restrict__ bias, const float* __restrict__ Res,
                            float* __restrict__ C,
                            int M, int Nn, int K, int lda, int ldb, int ldc, int zdiv,
                            long long sA1, long long sA2, long long sB1, long long sB2,
                            long long sC1, long long sC2)
{
    const int BM = 64, BN = 64, BK = 16;
    int tid = threadIdx.x;                 // 256 threads
    int tx = tid & 15, ty = tid >> 4;      // 16x16 thread grid, 4x4 each
    int rowBase = blockIdx.y * BM;
    int colBase = blockIdx.x * BN;
    int zb = blockIdx.z / zdiv, zh = blockIdx.z - zb*zdiv;
    const float* Ab = A + zb*sA1 + zh*sA2;
    const float* Bb = Bm + zb*sB1 + zh*sB2;
    float*       Cb = C + zb*sC1 + zh*sC2;
    const float* Rb = (EPI == 2) ? (Res + zb*sC1 + zh*sC2) : nullptr;

    __shared__ float As[BK][BM];
    __shared__ float Bs[BK][BN];

    float acc[4][4] = {};
    int a_row = tid >> 2;                  // 0..63
    int a_k4  = (tid & 3) * 4;             // 0,4,8,12

    for (int k0 = 0; k0 < K; k0 += BK) {
        // load A tile (transposed into smem)
        {
            int gr = rowBase + a_row;
            bool rok = gr < M;
            const float* ap = Ab + (long long)gr * lda + k0 + a_k4;
            #pragma unroll
            for (int t = 0; t < 4; t++) {
                int gk = k0 + a_k4 + t;
                As[a_k4 + t][a_row] = (rok && gk < K) ? ap[t] : 0.0f;
            }
        }
        if (!TRANSB) {
            int bk = tid >> 4;             // 0..15
            int bc = (tid & 15) * 4;       // 0..60
            int gk = k0 + bk;
            int gc = colBase + bc;
            const float* bp = Bb + (long long)gk * ldb + gc;
            bool kok = gk < K;
            #pragma unroll
            for (int t = 0; t < 4; t++)
                Bs[bk][bc + t] = (kok && (gc + t) < Nn) ? bp[t] : 0.0f;
        } else {
            int bn  = tid >> 2;            // 0..63
            int bk4 = (tid & 3) * 4;
            int gn = colBase + bn;
            bool nok = gn < Nn;
            const float* bp = Bb + (long long)gn * ldb + k0 + bk4;
            #pragma unroll
            for (int t = 0; t < 4; t++) {
                int gk = k0 + bk4 + t;
                Bs[bk4 + t][bn] = (nok && gk < K) ? bp[t] : 0.0f;
            }
        }
        __syncthreads();
        #pragma unroll
        for (int kk = 0; kk < BK; kk++) {
            float4 ra = *reinterpret_cast<const float4*>(&As[kk][ty*4]);
            float4 rb = *reinterpret_cast<const float4*>(&Bs[kk][tx*4]);
            float av[4] = {ra.x, ra.y, ra.z, ra.w};
            float bv[4] = {rb.x, rb.y, rb.z, rb.w};
            #pragma unroll
            for (int i = 0; i < 4; i++)
                #pragma unroll
                for (int j = 0; j < 4; j++)
                    acc[i][j] += av[i] * bv[j];
        }
        __syncthreads();
    }

    #pragma unroll
    for (int i = 0; i < 4; i++) {
        int gr = rowBase + ty*4 + i;
        if (gr >= M) continue;
        #pragma unroll
        for (int j = 0; j < 4; j++) {
            int gc = colBase + tx*4 + j;
            if (gc >= Nn) continue;
            float vv = acc[i][j] + (bias ? bias[gc] : 0.0f);
            if (EPI == 1) vv = gelu_f(vv);
            if (EPI == 2) vv += Rb[(long long)gr * ldc + gc];
            Cb[(long long)gr * ldc + gc] = vv;
        }
    }
}

// ---------------- im2col for 16x16 stride-16 patches -----------------------
__global__ void im2col_kernel(const float* __restrict__ img, float* __restrict__ out) {
    long long total = (long long)MPATCH * 768;
    long long stride = (long long)gridDim.x * blockDim.x;
    for (long long idx = (long long)blockIdx.x * blockDim.x + threadIdx.x; idx < total; idx += stride) {
        int kk = (int)(idx % 768);
        long long row = idx / 768;
        int b = (int)(row / NP_);
        int p = (int)(row % NP_);
        int ph = p / 14, pw = p % 14;
        int c = kk >> 8;
        int rem = kk & 255;
        int i = rem >> 4, j = rem & 15;
        out[idx] = img[(((long long)b*3 + c)*224 + (ph*16 + i))*224 + (pw*16 + j)];
    }
}

// ---------------- cls + patches + pos_emb assemble -------------------------
__global__ void assemble_kernel(const float* __restrict__ po, const float* __restrict__ cls,
                                const float* __restrict__ pos, float* __restrict__ x) {
    long long total = (long long)MTOK * D_;
    long long stride = (long long)gridDim.x * blockDim.x;
    for (long long idx = (long long)blockIdx.x * blockDim.x + threadIdx.x; idx < total; idx += stride) {
        int d = (int)(idx % D_);
        long long row = idx / D_;
        int b = (int)(row / N_);
        int n = (int)(row % N_);
        float v = (n == 0) ? cls[d] : po[((long long)b*NP_ + (n-1))*D_ + d];
        x[idx] = v + pos[(long long)n*D_ + d];
    }
}

// ---------------- LayerNorm (one 256-thread block per row of 768) ----------
__global__ void ln_kernel(const float* __restrict__ in, float* __restrict__ out,
                          const float* __restrict__ g, const float* __restrict__ bb) {
    int row = blockIdx.x;
    const float* ip = in + (long long)row * D_;
    float*       op = out + (long long)row * D_;
    __shared__ float s1[256], s2[256];
    float sum = 0.0f, sq = 0.0f;
    float vv[3];
    int c = 0;
    for (int d = threadIdx.x; d < D_; d += 256) {
        float v = ip[d];
        vv[c++] = v; sum += v; sq += v*v;
    }
    s1[threadIdx.x] = sum; s2[threadIdx.x] = sq;
    __syncthreads();
    for (int o = 128; o > 0; o >>= 1) {
        if (threadIdx.x < o) { s1[threadIdx.x] += s1[threadIdx.x+o]; s2[threadIdx.x] += s2[threadIdx.x+o]; }
        __syncthreads();
    }
    float mu = s1[0] * (1.0f / D_);
    float var = s2[0] * (1.0f / D_) - mu*mu;
    float rs = rsqrtf(var + 1e-5f);
    c = 0;
    for (int d = threadIdx.x; d < D_; d += 256)
        op[d] = (vv[c++] - mu) * rs * g[d] + bb[d];
}

// ---------------- row softmax (one warp per row of `cols`) -----------------
__global__ void softmax_kernel(float* __restrict__ s, long long rows, int cols, float scale) {
    long long warp = ((long long)blockIdx.x * blockDim.x + threadIdx.x) >> 5;
    int lane = threadIdx.x & 31;
    if (warp >= rows) return;
    float* r = s + warp * cols;
    float vals[8];
    int cnt = 0;
    float mx = -1e30f;
    for (int m = lane; m < cols; m += 32) {
        float v = r[m] * scale;
        vals[cnt++] = v;
        mx = fmaxf(mx, v);
    }
    for (int o = 16; o; o >>= 1) mx = fmaxf(mx, __shfl_xor_sync(0xffffffffu, mx, o));
    float sum = 0.0f;
    for (int t = 0; t < cnt; t++) { vals[t] = __expf(vals[t] - mx); sum += vals[t]; }
    for (int o = 16; o; o >>= 1) sum += __shfl_xor_sync(0xffffffffu, sum, o);
    float inv = 1.0f / sum;
    cnt = 0;
    for (int m = lane; m < cols; m += 32) r[m] = vals[cnt++] * inv;
}

// ---------------- mean pool over tokens ------------------------------------
__global__ void pool_kernel(const float* __restrict__ x, float* __restrict__ out) {
    int b = blockIdx.x;
    for (int d = threadIdx.x; d < D_; d += blockDim.x) {
        float s = 0.0f;
        const float* p = x + ((long long)b * N_) * D_ + d;
        for (int n = 0; n < N_; n++) s += p[(long long)n * D_];
        out[b*D_ + d] = s * (1.0f / N_);
    }
}

// ---------------- launcher --------------------------------------------------
extern "C" void kernel_launch(void* const* d_in, const int* in_sizes, int n_in,
                              void* d_out, int out_size) {
    const float* imgs    = (const float*)d_in[0];
    const float* patch_w = (const float*)d_in[1];
    const float* patch_b = (const float*)d_in[2];
    const float* cls_tok = (const float*)d_in[3];
    const float* pos_emb = (const float*)d_in[4];
    const float* ln1_g   = (const float*)d_in[5];
    const float* ln1_b   = (const float*)d_in[6];
    const float* wq      = (const float*)d_in[7];
    const float* bq      = (const float*)d_in[8];
    const float* wk      = (const float*)d_in[9];
    const float* bk      = (const float*)d_in[10];
    const float* wv      = (const float*)d_in[11];
    const float* bv      = (const float*)d_in[12];
    const float* wo      = (const float*)d_in[13];
    const float* bo      = (const float*)d_in[14];
    const float* ln2_g   = (const float*)d_in[15];
    const float* ln2_b   = (const float*)d_in[16];
    const float* w1      = (const float*)d_in[17];
    const float* b1      = (const float*)d_in[18];
    const float* w2      = (const float*)d_in[19];
    const float* b2      = (const float*)d_in[20];
    const float* hn_g    = (const float*)d_in[21];
    const float* hn_b    = (const float*)d_in[22];
    const float* hw      = (const float*)d_in[23];
    const float* hb      = (const float*)d_in[24];
    float* outp = (float*)d_out;

    float *x, *h, *q, *k, *v, *o, *mlp, *sc, *col, *po, *pool, *pln;
    cudaGetSymbolAddress((void**)&x,    g_x);
    cudaGetSymbolAddress((void**)&h,    g_h);
    cudaGetSymbolAddress((void**)&q,    g_q);
    cudaGetSymbolAddress((void**)&k,    g_k);
    cudaGetSymbolAddress((void**)&v,    g_v);
    cudaGetSymbolAddress((void**)&o,    g_o);
    cudaGetSymbolAddress((void**)&mlp,  g_mlp);
    cudaGetSymbolAddress((void**)&sc,   g_sc);
    cudaGetSymbolAddress((void**)&col,  g_col);
    cudaGetSymbolAddress((void**)&po,   g_po);
    cudaGetSymbolAddress((void**)&pool, g_pool);
    cudaGetSymbolAddress((void**)&pln,  g_pln);

    // --- patch embedding ---
    im2col_kernel<<<4096, 256>>>(imgs, col);
    gemm_kernel<true, 0><<<dim3(12, 98, 1), 256>>>(col, patch_w, patch_b, nullptr, po,
        MPATCH, D_, 768, 768, 768, 768, 1, 0, 0, 0, 0, 0, 0);
    assemble_kernel<<<4096, 256>>>(po, cls_tok, pos_emb, x);

    const long long sQKV_b = (long long)N_ * D_;   // batch stride inside [B,N,D]
    const long long sQKV_h = DH_;                  // head stride (column offset)
    const long long sSC_b  = (long long)HEADS_ * SROW;
    const long long sSC_h  = SROW;

    for (int i = 0; i < L_; i++) {
        const float* Wq = wq + (long long)i*D_*D_;  const float* Bq = bq + (long long)i*D_;
        const float* Wk = wk + (long long)i*D_*D_;  const float* Bk = bk + (long long)i*D_;
        const float* Wv = wv + (long long)i*D_*D_;  const float* Bv = bv + (long long)i*D_;
        const float* Wo = wo + (long long)i*D_*D_;  const float* Bo = bo + (long long)i*D_;
        const float* W1 = w1 + (long long)i*D_*MLP_;  const float* B1 = b1 + (long long)i*MLP_;
        const float* W2 = w2 + (long long)i*MLP_*D_;  const float* B2 = b2 + (long long)i*D_;

        ln_kernel<<<MTOK, 256>>>(x, h, ln1_g + (long long)i*D_, ln1_b + (long long)i*D_);

        dim3 gdd(12, 99, 1);   // [6304 x 768] x 768
        gemm_kernel<false, 0><<<gdd, 256>>>(h, Wq, Bq, nullptr, q,
            MTOK, D_, D_, D_, D_, D_, 1, 0,0, 0,0, 0,0);
        gemm_kernel<false, 0><<<gdd, 256>>>(h, Wk, Bk, nullptr, k,
            MTOK, D_, D_, D_, D_, D_, 1, 0,0, 0,0, 0,0);
        gemm_kernel<false, 0><<<gdd, 256>>>(h, Wv, Bv, nullptr, v,
            MTOK, D_, D_, D_, D_, D_, 1, 0,0, 0,0, 0,0);

        // S = Q @ K^T   per (b,h):  [197 x 197] , K = 64
        gemm_kernel<true, 0><<<dim3(4, 4, B_*HEADS_), 256>>>(q, k, nullptr, nullptr, sc,
            N_, N_, DH_, D_, D_, N_, HEADS_,
            sQKV_b, sQKV_h, sQKV_b, sQKV_h, sSC_b, sSC_h);

        long long srows = (long long)B_ * HEADS_ * N_;
        int smx_blocks = (int)((srows*32 + 255) / 256);
        softmax_kernel<<<smx_blocks, 256>>>(sc, srows, N_, 0.125f);

        // O = P @ V     per (b,h):  [197 x 64] , K = 197
        gemm_kernel<false, 0><<<dim3(1, 4, B_*HEADS_), 256>>>(sc, v, nullptr, nullptr, o,
            N_, DH_, N_, N_, D_, D_, HEADS_,
            sSC_b, sSC_h, sQKV_b, sQKV_h, sQKV_b, sQKV_h);

        // x = x + O @ Wo + bo
        gemm_kernel<false, 2><<<gdd, 256>>>(o, Wo, Bo, x, x,
            MTOK, D_, D_, D_, D_, D_, 1, 0,0, 0,0, 0,0);

        ln_kernel<<<MTOK, 256>>>(x, h, ln2_g + (long long)i*D_, ln2_b + (long long)i*D_);

        // mlp = gelu(h @ W1 + b1)
        gemm_kernel<false, 1><<<dim3(48, 99, 1), 256>>>(h, W1, B1, nullptr, mlp,
            MTOK, MLP_, D_, D_, MLP_, MLP_, 1, 0,0, 0,0, 0,0);
        // x = x + mlp @ W2 + b2
        gemm_kernel<false, 2><<<gdd, 256>>>(mlp, W2, B2, x, x,
            MTOK, D_, MLP_, MLP_, D_, D_, 1, 0,0, 0,0, 0,0);
    }

    pool_kernel<<<B_, 256>>>(x, pool);
    ln_kernel<<<B_, 256>>>(pool, pln, hn_g, hn_b);
    gemm_kernel<false, 0><<<dim3(16, 1, 1), 256>>>(pln, hw, hb, nullptr, outp,
        B_, NC_, D_, D_, NC_, NC_, 1, 0,0, 0,0, 0,0);
}